// round 1
// baseline (speedup 1.0000x reference)
#include <cuda_runtime.h>
#include <cuda_bf16.h>

// EdgeAtt: B=64, L=512, D=512
//   e_i[b,l] = nf[b,l,:] . w_a[:D];  e_j[b,l] = nf[b,l,:] . w_a[D:]
//   e[b,i,j] = leaky_relu(e_i + e_j + bias, 0.2), masked cols j>=len -> -1e9
//   A = softmax_j(e);  rows i>=len zeroed.

#define L_DIM 512
#define D_DIM 512
#define NEG_INF -1e9f
#define SLOPE 0.2f

// scratch for projections (B*L = 32768 each)
__device__ float g_ei[64 * L_DIM];
__device__ float g_ej[64 * L_DIM];

// ---------------- kernel 1: dual projection, warp per row ----------------
__global__ void __launch_bounds__(256) k_proj(const float* __restrict__ nf,
                                              const float* __restrict__ wa,
                                              int n_rows) {
    int warp = (blockIdx.x * blockDim.x + threadIdx.x) >> 5;
    int lane = threadIdx.x & 31;
    if (warp >= n_rows) return;

    const float4* row = reinterpret_cast<const float4*>(nf + (size_t)warp * D_DIM);
    const float4* w1  = reinterpret_cast<const float4*>(wa);
    const float4* w2  = reinterpret_cast<const float4*>(wa + D_DIM);

    float s1 = 0.f, s2 = 0.f;
#pragma unroll
    for (int t = 0; t < 4; t++) {
        int idx = lane + t * 32;          // 128 float4 = 512 floats
        float4 v = row[idx];
        float4 a = __ldg(&w1[idx]);
        float4 b = __ldg(&w2[idx]);
        s1 += v.x * a.x + v.y * a.y + v.z * a.z + v.w * a.w;
        s2 += v.x * b.x + v.y * b.y + v.z * b.z + v.w * b.w;
    }
#pragma unroll
    for (int o = 16; o; o >>= 1) {
        s1 += __shfl_xor_sync(0xffffffffu, s1, o);
        s2 += __shfl_xor_sync(0xffffffffu, s2, o);
    }
    if (lane == 0) {
        g_ei[warp] = s1;
        g_ej[warp] = s2;
    }
}

// ---------------- kernel 2: masked softmax, warp per output row ----------------
// grid: (L/8, B), block 256 (8 warps -> 8 rows), e_j[b,:] staged in smem
__global__ void __launch_bounds__(256) k_soft(const float* __restrict__ ba,
                                              const int* __restrict__ tlen,
                                              float* __restrict__ out) {
    __shared__ float sej[L_DIM];
    const int b   = blockIdx.y;
    const int tid = threadIdx.x;

    sej[tid]       = g_ej[b * L_DIM + tid];
    sej[tid + 256] = g_ej[b * L_DIM + tid + 256];
    __syncthreads();

    const int len   = tlen[b];
    const float bias = __ldg(ba);

    const int warp = tid >> 5;
    const int lane = tid & 31;
    const int i    = blockIdx.x * 8 + warp;

    float* orow = out + ((size_t)b * L_DIM + i) * L_DIM;

    if (i >= len) {
        // zero row (output is poisoned; must write everything)
        float4 z = make_float4(0.f, 0.f, 0.f, 0.f);
        float4* o4 = reinterpret_cast<float4*>(orow);
#pragma unroll
        for (int t = 0; t < 4; t++) o4[lane + t * 32] = z;
        return;
    }

    const float ei = g_ei[b * L_DIM + i] + bias;

    float x[16];
    float m = -1e30f;
#pragma unroll
    for (int t = 0; t < 16; t++) {
        int j = lane + t * 32;
        float v = ei + sej[j];
        v = v > 0.f ? v : SLOPE * v;            // leaky relu
        v = (j < len) ? v : NEG_INF;
        x[t] = v;
        m = fmaxf(m, v);
    }
#pragma unroll
    for (int o = 16; o; o >>= 1) m = fmaxf(m, __shfl_xor_sync(0xffffffffu, m, o));

    float s = 0.f;
#pragma unroll
    for (int t = 0; t < 16; t++) {
        int j = lane + t * 32;
        float p = (j < len) ? __expf(x[t] - m) : 0.f;
        x[t] = p;
        s += p;
    }
#pragma unroll
    for (int o = 16; o; o >>= 1) s += __shfl_xor_sync(0xffffffffu, s, o);

    const float inv = 1.f / s;
#pragma unroll
    for (int t = 0; t < 16; t++) {
        int j = lane + t * 32;                  // coalesced 128B per t
        orow[j] = x[t] * inv;
    }
}

extern "C" void kernel_launch(void* const* d_in, const int* in_sizes, int n_in,
                              void* d_out, int out_size) {
    const float* nf   = (const float*)d_in[0];   // [B, L, D]
    const float* wa   = (const float*)d_in[1];   // [2D]
    const float* ba   = (const float*)d_in[2];   // [1]
    const int*   tlen = (const int*)d_in[3];     // [B]
    float* out = (float*)d_out;                  // [B, L, L]

    const int B = in_sizes[3];
    const int n_rows = B * L_DIM;

    // kernel 1: warp per row, 8 warps/block
    k_proj<<<(n_rows + 7) / 8, 256>>>(nf, wa, n_rows);

    // kernel 2: 8 rows/block
    dim3 grid(L_DIM / 8, B);
    k_soft<<<grid, 256>>>(ba, tlen, out);
}

// round 2
// speedup vs baseline: 1.0195x; 1.0195x over previous
#include <cuda_runtime.h>
#include <cuda_bf16.h>

// EdgeAtt: B=64, L=512, D=512
//   e_i[b,l] = nf[b,l,:] . w_a[:D];  e_j[b,l] = nf[b,l,:] . w_a[D:]
//   e[b,i,j] = leaky_relu(e_i + e_j + bias, 0.2), cols j>=len -> -1e9
//   A = softmax_j(e);  rows i>=len zeroed.

#define L_DIM 512
#define D_DIM 512
#define SLOPE 0.2f

__device__ float g_ei[64 * L_DIM];
__device__ float g_ej[64 * L_DIM];

// ---------------- kernel 1: dual projection, warp per row ----------------
__global__ void __launch_bounds__(256) k_proj(const float* __restrict__ nf,
                                              const float* __restrict__ wa,
                                              int n_rows) {
    int warp = (blockIdx.x * blockDim.x + threadIdx.x) >> 5;
    int lane = threadIdx.x & 31;
    if (warp >= n_rows) return;

    const float4* row = reinterpret_cast<const float4*>(nf + (size_t)warp * D_DIM);
    const float4* w1  = reinterpret_cast<const float4*>(wa);
    const float4* w2  = reinterpret_cast<const float4*>(wa + D_DIM);

    float s1 = 0.f, s2 = 0.f;
#pragma unroll
    for (int t = 0; t < 4; t++) {
        int idx = lane + t * 32;          // 128 float4 = 512 floats
        float4 v = row[idx];
        float4 a = __ldg(&w1[idx]);
        float4 b = __ldg(&w2[idx]);
        s1 += v.x * a.x + v.y * a.y + v.z * a.z + v.w * a.w;
        s2 += v.x * b.x + v.y * b.y + v.z * b.z + v.w * b.w;
    }
#pragma unroll
    for (int o = 16; o; o >>= 1) {
        s1 += __shfl_xor_sync(0xffffffffu, s1, o);
        s2 += __shfl_xor_sync(0xffffffffu, s2, o);
    }
    if (lane == 0) {
        g_ei[warp] = s1;
        g_ej[warp] = s2;
    }
}

// ---------------- kernel 2: masked softmax, warp per output row ----------------
// grid (L/8, B), block 256. Row max computed analytically from max(e_j) since
// leaky_relu is monotonic: m_row = lrelu(ei + max_valid_ej + bias).
__global__ void __launch_bounds__(256) k_soft(const float* __restrict__ ba,
                                              const int* __restrict__ tlen,
                                              float* __restrict__ out) {
    __shared__ float sej[L_DIM];
    __shared__ float smax[8];

    const int b   = blockIdx.y;
    const int tid = threadIdx.x;
    const int warp = tid >> 5;
    const int lane = tid & 31;

    const float v0 = g_ej[b * L_DIM + tid];
    const float v1 = g_ej[b * L_DIM + tid + 256];
    sej[tid]       = v0;
    sej[tid + 256] = v1;

    const int len = tlen[b];

    // block max over valid e_j
    float mv = (tid < len) ? v0 : -1e30f;
    if (tid + 256 < len) mv = fmaxf(mv, v1);
#pragma unroll
    for (int o = 16; o; o >>= 1) mv = fmaxf(mv, __shfl_xor_sync(0xffffffffu, mv, o));
    if (lane == 0) smax[warp] = mv;
    __syncthreads();

    float mxej = smax[0];
#pragma unroll
    for (int k = 1; k < 8; k++) mxej = fmaxf(mxej, smax[k]);

    const int i = blockIdx.x * 8 + warp;
    float4* orow4 = reinterpret_cast<float4*>(out + ((size_t)b * L_DIM + i) * L_DIM);

    if (i >= len) {
        float4 z = make_float4(0.f, 0.f, 0.f, 0.f);
#pragma unroll
        for (int t = 0; t < 4; t++) orow4[t * 32 + lane] = z;
        return;
    }

    const float bias = __ldg(ba);
    const float ei = g_ei[b * L_DIM + i] + bias;
    const float mraw = ei + mxej;
    const float m = mraw > 0.f ? mraw : SLOPE * mraw;  // exact row max

    float4 p[4];
    float s = 0.f;
#pragma unroll
    for (int t = 0; t < 4; t++) {
        const int j0 = t * 128 + lane * 4;
        float4 e4 = *reinterpret_cast<const float4*>(&sej[j0]);
        const int rem = len - j0;   // component k valid iff k < rem

        float v, pe;
        v = ei + e4.x; v = v > 0.f ? v : SLOPE * v;
        pe = (0 < rem) ? __expf(v - m) : 0.f; p[t].x = pe; s += pe;
        v = ei + e4.y; v = v > 0.f ? v : SLOPE * v;
        pe = (1 < rem) ? __expf(v - m) : 0.f; p[t].y = pe; s += pe;
        v = ei + e4.z; v = v > 0.f ? v : SLOPE * v;
        pe = (2 < rem) ? __expf(v - m) : 0.f; p[t].z = pe; s += pe;
        v = ei + e4.w; v = v > 0.f ? v : SLOPE * v;
        pe = (3 < rem) ? __expf(v - m) : 0.f; p[t].w = pe; s += pe;
    }
#pragma unroll
    for (int o = 16; o; o >>= 1) s += __shfl_xor_sync(0xffffffffu, s, o);

    const float inv = 1.f / s;
#pragma unroll
    for (int t = 0; t < 4; t++) {
        float4 r;
        r.x = p[t].x * inv; r.y = p[t].y * inv;
        r.z = p[t].z * inv; r.w = p[t].w * inv;
        orow4[t * 32 + lane] = r;   // lanes cover 512B contiguous per t
    }
}

extern "C" void kernel_launch(void* const* d_in, const int* in_sizes, int n_in,
                              void* d_out, int out_size) {
    const float* nf   = (const float*)d_in[0];   // [B, L, D]
    const float* wa   = (const float*)d_in[1];   // [2D]
    const float* ba   = (const float*)d_in[2];   // [1]
    const int*   tlen = (const int*)d_in[3];     // [B]
    float* out = (float*)d_out;                  // [B, L, L]

    const int B = in_sizes[3];
    const int n_rows = B * L_DIM;

    k_proj<<<(n_rows + 7) / 8, 256>>>(nf, wa, n_rows);

    dim3 grid(L_DIM / 8, B);
    k_soft<<<grid, 256>>>(ba, tlen, out);
}